// round 14
// baseline (speedup 1.0000x reference)
#include <cuda_runtime.h>
#include <cuda_bf16.h>

// CBIndirectionLookup — persistent fused kernel, 4 rows/thread (MLP 8).
//   out[i] = (float) results[p] where patterns[p] == x[i] elementwise.
// key(row) = sum_j (word_j != 0) << j is a perfect hash over the 256 unique
// pattern rows ((word != 0) correct for int32 {0,1} and float32 {0,1} wires).
// Persistent grid: table built once per resident block; stream loop has 8
// front-batched LDG.128 per thread-iteration to keep the DRAM pipe fed.
//
// Output compared as float32; per-word dtype fix: a word >= 1024 can only be
// float bits of >= 1.0 (passthrough); words < 1024 are ints 0..999 (convert;
// int 0 -> 0.0f identical bits).

__device__ __forceinline__ int fix_word(int w) {
    return ((unsigned)w >= 1024u) ? w : __float_as_int((float)w);
}

__global__ void __launch_bounds__(256, 6)
cb_persist_kernel(const int4* __restrict__ x,        // N rows, 2 int4 each
                  const int4* __restrict__ pat4,     // [256] x 2 int4
                  const int4* __restrict__ res4,     // [256] x 1 int4
                  int4* __restrict__ out,            // N rows, 1 int4 each
                  int n)
{
    __shared__ int4 table[256];
    int t = threadIdx.x;

    // ---- one-time table build (sources L2-resident after first wave) -------
    int4 r  = res4[t];
    int4 p0 = pat4[2 * t];
    int4 p1 = pat4[2 * t + 1];

    int key =  (p0.x != 0)       | ((p0.y != 0) << 1)
            | ((p0.z != 0) << 2) | ((p0.w != 0) << 3)
            | ((p1.x != 0) << 4) | ((p1.y != 0) << 5)
            | ((p1.z != 0) << 6) | ((p1.w != 0) << 7);

    int4 row;
    row.x = fix_word(r.x);  row.y = fix_word(r.y);
    row.z = fix_word(r.z);  row.w = fix_word(r.w);
    table[key & 255] = row;
    __syncthreads();                       // the only barrier in the kernel

    #define PACK8(a, b) ( (a.x != 0)       | ((a.y != 0) << 1) \
                        | ((a.z != 0) << 2) | ((a.w != 0) << 3) \
                        | ((b.x != 0) << 4) | ((b.y != 0) << 5) \
                        | ((b.z != 0) << 6) | ((b.w != 0) << 7) )

    // ---- persistent stream loop: 4 rows/thread/iter, 8 LDG.128 in flight ---
    int stride = gridDim.x * 1024;
    for (int base = blockIdx.x * 1024 + t; base < n; base += stride) {
        int i1 = base + 256, i2 = base + 512, i3 = base + 768;
        bool v1 = (i1 < n), v2 = (i2 < n), v3 = (i3 < n);

        int4 a0, b0, a1, b1, a2, b2, a3, b3;
        a0 = x[2 * base];  b0 = x[2 * base + 1];
        if (v1) { a1 = x[2 * i1]; b1 = x[2 * i1 + 1]; }
        if (v2) { a2 = x[2 * i2]; b2 = x[2 * i2 + 1]; }
        if (v3) { a3 = x[2 * i3]; b3 = x[2 * i3 + 1]; }

        out[base] = table[PACK8(a0, b0) & 255];
        if (v1) out[i1] = table[PACK8(a1, b1) & 255];
        if (v2) out[i2] = table[PACK8(a2, b2) & 255];
        if (v3) out[i3] = table[PACK8(a3, b3) & 255];
    }
    #undef PACK8
}

extern "C" void kernel_launch(void* const* d_in, const int* in_sizes, int n_in,
                              void* d_out, int out_size)
{
    // Identify tensors by element count (order-independent):
    //   x: rows*8 (largest), patterns: 256*8 = 2048, results: 256*4 = 1024.
    int xi = 0;
    for (int k = 1; k < n_in; k++) if (in_sizes[k] > in_sizes[xi]) xi = k;
    const void* x = d_in[xi];
    const void* patterns = nullptr;
    const void* results  = nullptr;
    for (int k = 0; k < n_in; k++) {
        if (k == xi) continue;
        if (in_sizes[k] == 2048) patterns = d_in[k];
        else if (in_sizes[k] == 1024) results = d_in[k];
    }
    if ((!patterns || !results) && n_in >= 3) {   // size-rank fallback
        int pi = -1, ri = -1;
        for (int k = 0; k < n_in; k++) {
            if (k == xi) continue;
            if (pi < 0 || in_sizes[k] > in_sizes[pi]) { ri = pi; pi = k; }
            else if (ri < 0 || in_sizes[k] > in_sizes[ri]) ri = k;
        }
        patterns = d_in[pi]; results = d_in[ri];
    }

    long rows_x   = (long)in_sizes[xi] / 8;
    long rows_out = (long)out_size / 4;
    long rows = rows_x;
    if (rows_out > 0 && rows_out < rows) rows = rows_out;

    int n = (int)rows;
    int tiles = (n + 1023) / 1024;
    int blocks = 148 * 6;                       // resident set @ ~40 regs
    if (tiles < blocks) blocks = tiles;
    if (blocks > 0)
        cb_persist_kernel<<<blocks, 256>>>((const int4*)x,
                                           (const int4*)patterns,
                                           (const int4*)results,
                                           (int4*)d_out, n);
}

// round 15
// speedup vs baseline: 1.0389x; 1.0389x over previous
#include <cuda_runtime.h>
#include <cuda_bf16.h>

// CBIndirectionLookup — persistent kernel with TMA bulk double-buffering.
//   out[i] = (float) results[p] where patterns[p] == x[i] elementwise.
// key(row) = sum_j (word_j != 0) << j is a perfect hash over the 256 unique
// pattern rows ((word != 0) correct for int32 {0,1} and float32 {0,1} wires).
//
// Why TMA: LDG-based variants plateau at ~16 B/cyc/SM (per-SM outstanding-
// line budget ~8KB / ~550cyc DRAM latency), with DRAM only 55% active.
// cp.async.bulk transfers are mbarrier-tx tracked, not MSHR tracked, so the
// input stream can saturate the LTS path instead.
//
// Processing: 2 threads per row (each loads 16B from smem -> conflict-free
// LDS.128), shfl_xor merges the 4+4 bit halves, even lane gathers the table
// row and issues a coalesced STG.128.
//
// Output compared as float32; per-word dtype fix: word >= 1024 can only be
// float bits of >= 1.0 (passthrough); words < 1024 are ints 0..999 (convert).

#define TILE_ROWS  512
#define TILE_BYTES (TILE_ROWS * 32)

__device__ __forceinline__ int fix_word(int w) {
    return ((unsigned)w >= 1024u) ? w : __float_as_int((float)w);
}

__device__ __forceinline__ void mbar_wait(unsigned int mbar, int phase) {
    asm volatile(
        "{\n\t"
        ".reg .pred P;\n\t"
        "W_%=:\n\t"
        "mbarrier.try_wait.parity.shared::cta.b64 P, [%0], %1, 0x989680;\n\t"
        "@!P bra W_%=;\n\t"
        "}"
        :: "r"(mbar), "r"(phase) : "memory");
}

__device__ __forceinline__ void bulk_load(unsigned int smem_dst, const void* gmem_src,
                                          unsigned int bytes, unsigned int mbar) {
    asm volatile(
        "mbarrier.arrive.expect_tx.shared::cta.b64 _, [%0], %1;"
        :: "r"(mbar), "r"(bytes) : "memory");
    asm volatile(
        "cp.async.bulk.shared::cta.global.mbarrier::complete_tx::bytes "
        "[%0], [%1], %2, [%3];"
        :: "r"(smem_dst), "l"(gmem_src), "r"(bytes), "r"(mbar) : "memory");
}

__global__ void __launch_bounds__(256, 6)
cb_tma_kernel(const char* __restrict__ xb,       // N rows x 32 bytes
              const int4* __restrict__ pat4,     // [256] x 2 int4
              const int4* __restrict__ res4,     // [256] x 1 int4
              int4* __restrict__ out,            // N rows x 1 int4
              int n)
{
    __shared__ __align__(16) char buf[2][TILE_BYTES];
    __shared__ int4 table[256];
    __shared__ __align__(8) unsigned long long mbar_store[2];

    int t = threadIdx.x;
    unsigned int mb0 = (unsigned int)__cvta_generic_to_shared(&mbar_store[0]);
    unsigned int mb1 = (unsigned int)__cvta_generic_to_shared(&mbar_store[1]);
    unsigned int sb0 = (unsigned int)__cvta_generic_to_shared(&buf[0][0]);
    unsigned int sb1 = (unsigned int)__cvta_generic_to_shared(&buf[1][0]);

    if (t == 0) {
        asm volatile("mbarrier.init.shared::cta.b64 [%0], 1;" :: "r"(mb0) : "memory");
        asm volatile("mbarrier.init.shared::cta.b64 [%0], 1;" :: "r"(mb1) : "memory");
    }

    // ---- one-time table build ----------------------------------------------
    {
        int4 r  = res4[t];
        int4 p0 = pat4[2 * t];
        int4 p1 = pat4[2 * t + 1];
        int key =  (p0.x != 0)       | ((p0.y != 0) << 1)
                | ((p0.z != 0) << 2) | ((p0.w != 0) << 3)
                | ((p1.x != 0) << 4) | ((p1.y != 0) << 5)
                | ((p1.z != 0) << 6) | ((p1.w != 0) << 7);
        int4 row;
        row.x = fix_word(r.x);  row.y = fix_word(r.y);
        row.z = fix_word(r.z);  row.w = fix_word(r.w);
        table[key & 255] = row;
    }
    __syncthreads();                 // table ready + mbarriers initialized

    int ntiles = (n + TILE_ROWS - 1) / TILE_ROWS;
    long first = blockIdx.x;
    if (first >= ntiles) return;     // uniform per block

    int pr = t >> 1;                 // pair index 0..127
    int h  = t & 1;                  // half: 0 = channels 0-3, 1 = channels 4-7

    // prologue: kick off tile 0 for this block
    if (t == 0) {
        long tb = first;
        int rem = n - (int)(tb * TILE_ROWS);
        unsigned int bytes = (rem >= TILE_ROWS ? TILE_BYTES : rem * 32);
        bulk_load(sb0, xb + tb * (long)TILE_BYTES, bytes, mb0);
    }

    int ph0 = 0, ph1 = 0;
    int k = 0;
    for (long tb = first; tb < ntiles; tb += gridDim.x, k++) {
        // issue next tile into the other stage (buffer freed by prev iter's sync)
        long nxt = tb + gridDim.x;
        if (nxt < ntiles && t == 0) {
            int rem_n = n - (int)(nxt * TILE_ROWS);
            unsigned int bytes = (rem_n >= TILE_ROWS ? TILE_BYTES : rem_n * 32);
            bulk_load(((k + 1) & 1) ? sb1 : sb0,
                      xb + nxt * (long)TILE_BYTES, bytes,
                      ((k + 1) & 1) ? mb1 : mb0);
        }

        int s = k & 1;
        if (s == 0) { mbar_wait(mb0, ph0); ph0 ^= 1; }
        else        { mbar_wait(mb1, ph1); ph1 ^= 1; }

        const char* bp = buf[s];
        int base_row = (int)(tb * TILE_ROWS);
        int rem = n - base_row; if (rem > TILE_ROWS) rem = TILE_ROWS;

        #pragma unroll
        for (int j = 0; j < 4; j++) {
            int row = pr + 128 * j;                 // rows 0..511, lane-sequential smem
            int4 v = *(const int4*)(bp + row * 32 + h * 16);   // conflict-free LDS.128
            int bits =  (v.x != 0)       | ((v.y != 0) << 1)
                     | ((v.z != 0) << 2) | ((v.w != 0) << 3);
            int other = __shfl_xor_sync(0xffffffffu, bits, 1);
            int idx = h ? (other | (bits << 4)) : (bits | (other << 4));
            if (h == 0 && row < rem)
                out[base_row + row] = table[idx & 255];   // coalesced half-warp STG.128
        }
        __syncthreads();             // all reads of buf[s] done before reuse
    }
}

extern "C" void kernel_launch(void* const* d_in, const int* in_sizes, int n_in,
                              void* d_out, int out_size)
{
    // Identify tensors by element count (order-independent):
    //   x: rows*8 (largest), patterns: 256*8 = 2048, results: 256*4 = 1024.
    int xi = 0;
    for (int k = 1; k < n_in; k++) if (in_sizes[k] > in_sizes[xi]) xi = k;
    const void* x = d_in[xi];
    const void* patterns = nullptr;
    const void* results  = nullptr;
    for (int k = 0; k < n_in; k++) {
        if (k == xi) continue;
        if (in_sizes[k] == 2048) patterns = d_in[k];
        else if (in_sizes[k] == 1024) results = d_in[k];
    }
    if ((!patterns || !results) && n_in >= 3) {   // size-rank fallback
        int pi = -1, ri = -1;
        for (int k = 0; k < n_in; k++) {
            if (k == xi) continue;
            if (pi < 0 || in_sizes[k] > in_sizes[pi]) { ri = pi; pi = k; }
            else if (ri < 0 || in_sizes[k] > in_sizes[ri]) ri = k;
        }
        patterns = d_in[pi]; results = d_in[ri];
    }

    long rows_x   = (long)in_sizes[xi] / 8;
    long rows_out = (long)out_size / 4;
    long rows = rows_x;
    if (rows_out > 0 && rows_out < rows) rows = rows_out;

    int n = (int)rows;
    int ntiles = (n + TILE_ROWS - 1) / TILE_ROWS;
    int blocks = 148 * 6;
    if (ntiles < blocks) blocks = ntiles;
    if (blocks > 0)
        cb_tma_kernel<<<blocks, 256>>>((const char*)x,
                                       (const int4*)patterns,
                                       (const int4*)results,
                                       (int4*)d_out, n);
}